// round 1
// baseline (speedup 1.0000x reference)
#include <cuda_runtime.h>
#include <math.h>

#define Bq 128
#define Uq 16
#define Dq 256
#define Nq 1024
#define Oq 256

// lr[b][u] scratch (device global: no allocations allowed)
__device__ float g_lr[Bq * Uq];

// ---------------------------------------------------------------------------
// Kernel 1: lr = softmax_u( (X[b,u,:] . alr[u,:]) / T )
// grid = 128 blocks (one per b), block = (32, 16): warp (y=u) does the dot.
// ---------------------------------------------------------------------------
__global__ void lr_kernel(const float* __restrict__ X,
                          const float* __restrict__ alr,
                          const float* __restrict__ temp) {
    const int b    = blockIdx.x;
    const int u    = threadIdx.y;
    const int lane = threadIdx.x;

    const float* xp = X + ((size_t)b * Uq + u) * Dq;
    const float* ap = alr + (size_t)u * Dq;
    float sum = 0.f;
#pragma unroll
    for (int d = lane; d < Dq; d += 32) sum += xp[d] * ap[d];
#pragma unroll
    for (int o = 16; o; o >>= 1) sum += __shfl_xor_sync(0xffffffffu, sum, o);

    __shared__ float logits[Uq];
    if (lane == 0) logits[u] = sum / temp[0];
    __syncthreads();

    if (threadIdx.y == 0 && lane == 0) {
        float mx = logits[0];
#pragma unroll
        for (int i = 1; i < Uq; i++) mx = fmaxf(mx, logits[i]);
        float e[Uq];
        float s = 0.f;
#pragma unroll
        for (int i = 0; i < Uq; i++) { e[i] = expf(logits[i] - mx); s += e[i]; }
        float inv = 1.f / s;
#pragma unroll
        for (int i = 0; i < Uq; i++) g_lr[b * Uq + i] = e[i] * inv;
    }
}

// ---------------------------------------------------------------------------
// Kernel 2: fused state update.
// Per u: C[b,m] = [X[:,u,:] | state[:,u,:]] @ [Win[u]; W[u]*sr[u]]  (K = 1280)
// epilogue: new_state = (1-lr)*s + lr*tanh(C + bias)
// 64x64x16 tile, 256 threads, 4x4 accum per thread.
// ---------------------------------------------------------------------------
__global__ void __launch_bounds__(256) state_kernel(
    const float* __restrict__ X, const float* __restrict__ state,
    const float* __restrict__ W, const float* __restrict__ Win,
    const float* __restrict__ bias, const float* __restrict__ sr,
    float* __restrict__ out_ns)
{
    const int u  = blockIdx.z;
    const int n0 = blockIdx.x * 64;   // output column (m) tile
    const int b0 = blockIdx.y * 64;   // batch row tile
    const float srv = sr[u];

    __shared__ float As[16][65];      // padded: conflict-free scalar stores
    __shared__ float Bs[16][64];      // float4 friendly

    const int t     = threadIdx.x;
    const int tx    = t & 15;         // col group
    const int ty    = t >> 4;         // row group
    const int a_row = t >> 2;         // 0..63
    const int a_k   = (t & 3) << 2;   // 0,4,8,12
    const int b_k   = t >> 4;         // 0..15
    const int b_col = (t & 15) << 2;  // 0..60

    float acc[4][4] = {};

    for (int kt = 0; kt < Dq + Nq; kt += 16) {
        // ---- load A (concatenated [X | state]) ----
        float4 av;
        {
            const int gb = b0 + a_row;
            const int k  = kt + a_k;
            const float* src = (k < Dq)
                ? (X     + ((size_t)gb * Uq + u) * Dq + k)
                : (state + ((size_t)gb * Uq + u) * Nq + (k - Dq));
            av = *reinterpret_cast<const float4*>(src);
        }
        // ---- load B (concatenated [Win; W*sr]) ----
        float4 bv;
        {
            const int k = kt + b_k;
            if (k < Dq) {
                bv = *reinterpret_cast<const float4*>(
                    Win + ((size_t)u * Dq + k) * Nq + n0 + b_col);
            } else {
                bv = *reinterpret_cast<const float4*>(
                    W + ((size_t)u * Nq + (k - Dq)) * Nq + n0 + b_col);
                bv.x *= srv; bv.y *= srv; bv.z *= srv; bv.w *= srv;
            }
        }
        __syncthreads();
        As[a_k + 0][a_row] = av.x;
        As[a_k + 1][a_row] = av.y;
        As[a_k + 2][a_row] = av.z;
        As[a_k + 3][a_row] = av.w;
        *reinterpret_cast<float4*>(&Bs[b_k][b_col]) = bv;
        __syncthreads();

#pragma unroll
        for (int k = 0; k < 16; k++) {
            float ar[4];
#pragma unroll
            for (int i = 0; i < 4; i++) ar[i] = As[k][ty * 4 + i];
            float4 bq = *reinterpret_cast<float4*>(&Bs[k][tx * 4]);
            float br[4] = {bq.x, bq.y, bq.z, bq.w};
#pragma unroll
            for (int i = 0; i < 4; i++)
#pragma unroll
                for (int j = 0; j < 4; j++)
                    acc[i][j] = fmaf(ar[i], br[j], acc[i][j]);
        }
    }

    // ---- epilogue: bias, tanh, lr-gated update ----
    const int gm = n0 + tx * 4;
#pragma unroll
    for (int i = 0; i < 4; i++) {
        const int bb = b0 + ty * 4 + i;
        const float lr  = g_lr[bb * Uq + u];
        const float oml = 1.f - lr;
        const float* srow = state  + ((size_t)bb * Uq + u) * Nq + gm;
        float*       orow = out_ns + ((size_t)bb * Uq + u) * Nq + gm;
#pragma unroll
        for (int j = 0; j < 4; j++) {
            float a = acc[i][j] + bias[u * Nq + gm + j];
            orow[j] = oml * srow[j] + lr * tanhf(a);
        }
    }
}

// ---------------------------------------------------------------------------
// Kernel 3: output = new_state @ Wout[u]   (per u: 128 x 256 x 1024)
// ---------------------------------------------------------------------------
__global__ void __launch_bounds__(256) out_kernel(
    const float* __restrict__ ns, const float* __restrict__ Wout,
    float* __restrict__ out2)
{
    const int u  = blockIdx.z;
    const int o0 = blockIdx.x * 64;
    const int b0 = blockIdx.y * 64;

    __shared__ float As[16][65];
    __shared__ float Bs[16][64];

    const int t     = threadIdx.x;
    const int tx    = t & 15;
    const int ty    = t >> 4;
    const int a_row = t >> 2;
    const int a_k   = (t & 3) << 2;
    const int b_k   = t >> 4;
    const int b_col = (t & 15) << 2;

    float acc[4][4] = {};

    for (int kt = 0; kt < Nq; kt += 16) {
        float4 av = *reinterpret_cast<const float4*>(
            ns + ((size_t)(b0 + a_row) * Uq + u) * Nq + kt + a_k);
        float4 bv = *reinterpret_cast<const float4*>(
            Wout + ((size_t)u * Nq + kt + b_k) * Oq + o0 + b_col);

        __syncthreads();
        As[a_k + 0][a_row] = av.x;
        As[a_k + 1][a_row] = av.y;
        As[a_k + 2][a_row] = av.z;
        As[a_k + 3][a_row] = av.w;
        *reinterpret_cast<float4*>(&Bs[b_k][b_col]) = bv;
        __syncthreads();

#pragma unroll
        for (int k = 0; k < 16; k++) {
            float ar[4];
#pragma unroll
            for (int i = 0; i < 4; i++) ar[i] = As[k][ty * 4 + i];
            float4 bq = *reinterpret_cast<float4*>(&Bs[k][tx * 4]);
            float br[4] = {bq.x, bq.y, bq.z, bq.w};
#pragma unroll
            for (int i = 0; i < 4; i++)
#pragma unroll
                for (int j = 0; j < 4; j++)
                    acc[i][j] = fmaf(ar[i], br[j], acc[i][j]);
        }
    }

    const int go = o0 + tx * 4;
#pragma unroll
    for (int i = 0; i < 4; i++) {
        const int bb = b0 + ty * 4 + i;
        float* orow = out2 + ((size_t)bb * Uq + u) * Oq + go;
#pragma unroll
        for (int j = 0; j < 4; j++) orow[j] = acc[i][j];
    }
}

// ---------------------------------------------------------------------------
extern "C" void kernel_launch(void* const* d_in, const int* in_sizes, int n_in,
                              void* d_out, int out_size) {
    const float* X     = (const float*)d_in[0];
    const float* state = (const float*)d_in[1];
    const float* W     = (const float*)d_in[2];
    const float* Win   = (const float*)d_in[3];
    const float* bias  = (const float*)d_in[4];
    const float* Wout  = (const float*)d_in[5];
    const float* sr    = (const float*)d_in[6];
    const float* alr   = (const float*)d_in[7];
    const float* temp  = (const float*)d_in[8];

    float* out_ns = (float*)d_out;                       // (B,U,N)
    float* out_o  = out_ns + (size_t)Bq * Uq * Nq;       // (B,U,O)

    lr_kernel<<<Bq, dim3(32, Uq)>>>(X, alr, temp);
    state_kernel<<<dim3(Nq / 64, Bq / 64, Uq), 256>>>(X, state, W, Win, bias, sr, out_ns);
    out_kernel<<<dim3(Oq / 64, Bq / 64, Uq), 256>>>(out_ns, Wout, out_o);
}

// round 2
// speedup vs baseline: 1.8306x; 1.8306x over previous
#include <cuda_runtime.h>
#include <math.h>

#define Bq 128
#define Uq 16
#define Dq 256
#define Nq 1024
#define Oq 256

__device__ float g_lr[Bq * Uq];

__device__ __forceinline__ unsigned f2tf(float f) {
    unsigned r;
    asm("cvt.rna.tf32.f32 %0, %1;" : "=r"(r) : "f"(f));
    return r;
}

__device__ __forceinline__ void mma_tf32(float* c, const unsigned* a, const unsigned* b) {
    asm volatile(
        "mma.sync.aligned.m16n8k8.row.col.f32.tf32.tf32.f32 "
        "{%0,%1,%2,%3},{%4,%5,%6,%7},{%8,%9},{%0,%1,%2,%3};"
        : "+f"(c[0]), "+f"(c[1]), "+f"(c[2]), "+f"(c[3])
        : "r"(a[0]), "r"(a[1]), "r"(a[2]), "r"(a[3]), "r"(b[0]), "r"(b[1]));
}

// ---------------------------------------------------------------------------
// Kernel 1: lr = softmax_u( (X[b,u,:] . alr[u,:]) / T )
// ---------------------------------------------------------------------------
__global__ void lr_kernel(const float* __restrict__ X,
                          const float* __restrict__ alr,
                          const float* __restrict__ temp) {
    const int b    = blockIdx.x;
    const int u    = threadIdx.y;
    const int lane = threadIdx.x;

    const float4* xp = (const float4*)(X + ((size_t)b * Uq + u) * Dq);
    const float4* ap = (const float4*)(alr + (size_t)u * Dq);
    float4 x0 = xp[lane], x1 = xp[lane + 32];
    float4 a0 = ap[lane], a1 = ap[lane + 32];
    float sum = x0.x * a0.x + x0.y * a0.y + x0.z * a0.z + x0.w * a0.w +
                x1.x * a1.x + x1.y * a1.y + x1.z * a1.z + x1.w * a1.w;
#pragma unroll
    for (int o = 16; o; o >>= 1) sum += __shfl_xor_sync(0xffffffffu, sum, o);

    __shared__ float logits[Uq];
    if (lane == 0) logits[u] = sum / temp[0];
    __syncthreads();

    if (threadIdx.y == 0 && lane == 0) {
        float mx = logits[0];
#pragma unroll
        for (int i = 1; i < Uq; i++) mx = fmaxf(mx, logits[i]);
        float e[Uq], s = 0.f;
#pragma unroll
        for (int i = 0; i < Uq; i++) { e[i] = expf(logits[i] - mx); s += e[i]; }
        float inv = 1.f / s;
#pragma unroll
        for (int i = 0; i < Uq; i++) g_lr[b * Uq + i] = e[i] * inv;
    }
}

// ---------------------------------------------------------------------------
// Shared tf32 MMA block body:
//   BM=64 (batch rows), BN=128 (output cols), BK=32
//   256 threads = 8 warps as 2(m) x 4(n); warp tile 32x32 = 2x4 m16n8k8 tiles
// A smem: [k][m] stride 72  -> (8k+m)%32 distinct across lanes (no conflicts)
// B smem: [k][n] stride 136 -> (8k+n)%32 distinct across lanes (no conflicts)
// ---------------------------------------------------------------------------
#define A_STRIDE 72
#define B_STRIDE 136

// ---------------------------------------------------------------------------
// Kernel 2: fused state update (K = D + N = 1280, concatenated [X|state] vs
// [Win; W*sr]); epilogue: new_state = (1-lr)*s + lr*tanh(C + bias)
// ---------------------------------------------------------------------------
__global__ void __launch_bounds__(256) state_kernel(
    const float* __restrict__ X, const float* __restrict__ state,
    const float* __restrict__ W, const float* __restrict__ Win,
    const float* __restrict__ bias, const float* __restrict__ sr,
    float* __restrict__ out_ns)
{
    const int u  = blockIdx.z;
    const int n0 = blockIdx.x * 128;
    const int b0 = blockIdx.y * 64;
    const float srv = sr[u];

    __shared__ unsigned As[32][A_STRIDE];
    __shared__ unsigned Bs[32][B_STRIDE];

    const int t      = threadIdx.x;
    const int wid    = t >> 5;
    const int lane   = t & 31;
    const int gid    = lane >> 2;
    const int tig    = lane & 3;
    const int warp_m = wid >> 2;      // 0..1
    const int warp_n = wid & 3;       // 0..3

    // global A loader mapping: m = t&63, k group = (t>>6)*8
    const int la_m = t & 63;
    const int la_k = (t >> 6) << 3;
    // global B loader mapping: n = (t&31)*4, k row = t>>5
    const int lb_n = (t & 31) << 2;
    const int lb_k = t >> 5;

    float acc[2][4][4] = {};

    for (int kt = 0; kt < Dq + Nq; kt += 32) {
        // ---- global loads ----
        float4 av0, av1;
        {
            const int gb = b0 + la_m;
            const int k  = kt + la_k;
            const float* src = (k < Dq)
                ? (X     + ((size_t)gb * Uq + u) * Dq + k)
                : (state + ((size_t)gb * Uq + u) * Nq + (k - Dq));
            av0 = *(const float4*)(src);
            av1 = *(const float4*)(src + 4);
        }
        float4 bv[4];
        {
#pragma unroll
            for (int r = 0; r < 4; r++) {
                const int k = kt + lb_k + r * 8;
                if (k < Dq) {
                    bv[r] = *(const float4*)(Win + ((size_t)u * Dq + k) * Nq + n0 + lb_n);
                } else {
                    bv[r] = *(const float4*)(W + ((size_t)u * Nq + (k - Dq)) * Nq + n0 + lb_n);
                    bv[r].x *= srv; bv[r].y *= srv; bv[r].z *= srv; bv[r].w *= srv;
                }
            }
        }
        __syncthreads();
        // ---- stage to smem (converted to tf32 bits) ----
        As[la_k + 0][la_m] = f2tf(av0.x);
        As[la_k + 1][la_m] = f2tf(av0.y);
        As[la_k + 2][la_m] = f2tf(av0.z);
        As[la_k + 3][la_m] = f2tf(av0.w);
        As[la_k + 4][la_m] = f2tf(av1.x);
        As[la_k + 5][la_m] = f2tf(av1.y);
        As[la_k + 6][la_m] = f2tf(av1.z);
        As[la_k + 7][la_m] = f2tf(av1.w);
#pragma unroll
        for (int r = 0; r < 4; r++) {
            unsigned* dst = &Bs[lb_k + r * 8][lb_n];
            dst[0] = f2tf(bv[r].x); dst[1] = f2tf(bv[r].y);
            dst[2] = f2tf(bv[r].z); dst[3] = f2tf(bv[r].w);
        }
        __syncthreads();

        // ---- MMA over 4 k8 steps ----
#pragma unroll
        for (int ks = 0; ks < 4; ks++) {
            const int kb = ks * 8;
            unsigned a[2][4], b[4][2];
#pragma unroll
            for (int mt = 0; mt < 2; mt++) {
                const int m = warp_m * 32 + mt * 16;
                a[mt][0] = As[kb + tig][m + gid];
                a[mt][1] = As[kb + tig][m + gid + 8];
                a[mt][2] = As[kb + tig + 4][m + gid];
                a[mt][3] = As[kb + tig + 4][m + gid + 8];
            }
#pragma unroll
            for (int nt = 0; nt < 4; nt++) {
                const int n = warp_n * 32 + nt * 8;
                b[nt][0] = Bs[kb + tig][n + gid];
                b[nt][1] = Bs[kb + tig + 4][n + gid];
            }
#pragma unroll
            for (int mt = 0; mt < 2; mt++)
#pragma unroll
                for (int nt = 0; nt < 4; nt++)
                    mma_tf32(acc[mt][nt], a[mt], b[nt]);
        }
    }

    // ---- epilogue ----
#pragma unroll
    for (int mt = 0; mt < 2; mt++) {
#pragma unroll
        for (int half = 0; half < 2; half++) {
            const int bb = b0 + warp_m * 32 + mt * 16 + gid + half * 8;
            const float lr  = g_lr[bb * Uq + u];
            const float oml = 1.f - lr;
            const float* srow = state  + ((size_t)bb * Uq + u) * Nq;
            float*       orow = out_ns + ((size_t)bb * Uq + u) * Nq;
#pragma unroll
            for (int nt = 0; nt < 4; nt++) {
                const int n = n0 + warp_n * 32 + nt * 8 + tig * 2;
#pragma unroll
                for (int j = 0; j < 2; j++) {
                    const float v = acc[mt][nt][half * 2 + j] + bias[u * Nq + n + j];
                    orow[n + j] = oml * srow[n + j] + lr * tanhf(v);
                }
            }
        }
    }
}

// ---------------------------------------------------------------------------
// Kernel 3: output = new_state @ Wout[u]   (per u: 128 x 256 x 1024)
// ---------------------------------------------------------------------------
__global__ void __launch_bounds__(256) out_kernel(
    const float* __restrict__ ns, const float* __restrict__ Wout,
    float* __restrict__ out2)
{
    const int u  = blockIdx.z;
    const int o0 = blockIdx.x * 128;
    const int b0 = blockIdx.y * 64;

    __shared__ unsigned As[32][A_STRIDE];
    __shared__ unsigned Bs[32][B_STRIDE];

    const int t      = threadIdx.x;
    const int wid    = t >> 5;
    const int lane   = t & 31;
    const int gid    = lane >> 2;
    const int tig    = lane & 3;
    const int warp_m = wid >> 2;
    const int warp_n = wid & 3;

    const int la_m = t & 63;
    const int la_k = (t >> 6) << 3;
    const int lb_n = (t & 31) << 2;
    const int lb_k = t >> 5;

    float acc[2][4][4] = {};

    for (int kt = 0; kt < Nq; kt += 32) {
        float4 av0, av1;
        {
            const float* src = ns + ((size_t)(b0 + la_m) * Uq + u) * Nq + kt + la_k;
            av0 = *(const float4*)(src);
            av1 = *(const float4*)(src + 4);
        }
        float4 bv[4];
#pragma unroll
        for (int r = 0; r < 4; r++) {
            const int k = kt + lb_k + r * 8;
            bv[r] = *(const float4*)(Wout + ((size_t)u * Nq + k) * Oq + o0 + lb_n);
        }
        __syncthreads();
        As[la_k + 0][la_m] = f2tf(av0.x);
        As[la_k + 1][la_m] = f2tf(av0.y);
        As[la_k + 2][la_m] = f2tf(av0.z);
        As[la_k + 3][la_m] = f2tf(av0.w);
        As[la_k + 4][la_m] = f2tf(av1.x);
        As[la_k + 5][la_m] = f2tf(av1.y);
        As[la_k + 6][la_m] = f2tf(av1.z);
        As[la_k + 7][la_m] = f2tf(av1.w);
#pragma unroll
        for (int r = 0; r < 4; r++) {
            unsigned* dst = &Bs[lb_k + r * 8][lb_n];
            dst[0] = f2tf(bv[r].x); dst[1] = f2tf(bv[r].y);
            dst[2] = f2tf(bv[r].z); dst[3] = f2tf(bv[r].w);
        }
        __syncthreads();

#pragma unroll
        for (int ks = 0; ks < 4; ks++) {
            const int kb = ks * 8;
            unsigned a[2][4], b[4][2];
#pragma unroll
            for (int mt = 0; mt < 2; mt++) {
                const int m = warp_m * 32 + mt * 16;
                a[mt][0] = As[kb + tig][m + gid];
                a[mt][1] = As[kb + tig][m + gid + 8];
                a[mt][2] = As[kb + tig + 4][m + gid];
                a[mt][3] = As[kb + tig + 4][m + gid + 8];
            }
#pragma unroll
            for (int nt = 0; nt < 4; nt++) {
                const int n = warp_n * 32 + nt * 8;
                b[nt][0] = Bs[kb + tig][n + gid];
                b[nt][1] = Bs[kb + tig + 4][n + gid];
            }
#pragma unroll
            for (int mt = 0; mt < 2; mt++)
#pragma unroll
                for (int nt = 0; nt < 4; nt++)
                    mma_tf32(acc[mt][nt], a[mt], b[nt]);
        }
    }

#pragma unroll
    for (int mt = 0; mt < 2; mt++) {
#pragma unroll
        for (int half = 0; half < 2; half++) {
            const int bb = b0 + warp_m * 32 + mt * 16 + gid + half * 8;
            float* orow = out2 + ((size_t)bb * Uq + u) * Oq;
#pragma unroll
            for (int nt = 0; nt < 4; nt++) {
                const int n = o0 + warp_n * 32 + nt * 8 + tig * 2;
                orow[n + 0] = acc[mt][nt][half * 2 + 0];
                orow[n + 1] = acc[mt][nt][half * 2 + 1];
            }
        }
    }
}

// ---------------------------------------------------------------------------
extern "C" void kernel_launch(void* const* d_in, const int* in_sizes, int n_in,
                              void* d_out, int out_size) {
    const float* X     = (const float*)d_in[0];
    const float* state = (const float*)d_in[1];
    const float* W     = (const float*)d_in[2];
    const float* Win   = (const float*)d_in[3];
    const float* bias  = (const float*)d_in[4];
    const float* Wout  = (const float*)d_in[5];
    const float* sr    = (const float*)d_in[6];
    const float* alr   = (const float*)d_in[7];
    const float* temp  = (const float*)d_in[8];

    float* out_ns = (float*)d_out;                  // (B,U,N)
    float* out_o  = out_ns + (size_t)Bq * Uq * Nq;  // (B,U,O)

    lr_kernel<<<Bq, dim3(32, Uq)>>>(X, alr, temp);
    state_kernel<<<dim3(Nq / 128, Bq / 64, Uq), 256>>>(X, state, W, Win, bias, sr, out_ns);
    out_kernel<<<dim3(Oq / 128, Bq / 64, Uq), 256>>>(out_ns, Wout, out_o);
}

// round 12
// speedup vs baseline: 3.5248x; 1.9254x over previous
#include <cuda_runtime.h>
#include <math.h>

#define Bq 128
#define Uq 16
#define Dq 256
#define Nq 1024
#define Oq 256

__device__ float g_lr[Bq * Uq];

__device__ __forceinline__ float fast_tanh(float x) {
    float y;
    asm("tanh.approx.f32 %0, %1;" : "=f"(y) : "f"(x));
    return y;
}

__device__ __forceinline__ void cp16(float* smem_dst, const float* gsrc) {
    unsigned s = (unsigned)__cvta_generic_to_shared(smem_dst);
    asm volatile("cp.async.cg.shared.global [%0], [%1], 16;\n" :: "r"(s), "l"(gsrc));
}
#define CP_COMMIT() asm volatile("cp.async.commit_group;\n" ::)
#define CP_WAIT1()  asm volatile("cp.async.wait_group 1;\n" ::)

__device__ __forceinline__ void mma_tf32(float* c, const float* a, const float* b) {
    asm volatile(
        "mma.sync.aligned.m16n8k8.row.col.f32.tf32.tf32.f32 "
        "{%0,%1,%2,%3},{%4,%5,%6,%7},{%8,%9},{%0,%1,%2,%3};"
        : "+f"(c[0]), "+f"(c[1]), "+f"(c[2]), "+f"(c[3])
        : "r"(__float_as_uint(a[0])), "r"(__float_as_uint(a[1])),
          "r"(__float_as_uint(a[2])), "r"(__float_as_uint(a[3])),
          "r"(__float_as_uint(b[0])), "r"(__float_as_uint(b[1])));
}

// ---------------------------------------------------------------------------
// Kernel 1: lr = softmax_u( (X[b,u,:] . alr[u,:]) / T )
// ---------------------------------------------------------------------------
__global__ void lr_kernel(const float* __restrict__ X,
                          const float* __restrict__ alr,
                          const float* __restrict__ temp) {
    const int b    = blockIdx.x;
    const int u    = threadIdx.y;
    const int lane = threadIdx.x;

    const float4* xp = (const float4*)(X + ((size_t)b * Uq + u) * Dq);
    const float4* ap = (const float4*)(alr + (size_t)u * Dq);
    float4 x0 = xp[lane], x1 = xp[lane + 32];
    float4 a0 = ap[lane], a1 = ap[lane + 32];
    float sum = x0.x * a0.x + x0.y * a0.y + x0.z * a0.z + x0.w * a0.w +
                x1.x * a1.x + x1.y * a1.y + x1.z * a1.z + x1.w * a1.w;
#pragma unroll
    for (int o = 16; o; o >>= 1) sum += __shfl_xor_sync(0xffffffffu, sum, o);

    __shared__ float logits[Uq];
    if (lane == 0) logits[u] = sum / temp[0];
    __syncthreads();

    if (threadIdx.y == 0) {          // one warp does the 16-way softmax
        float l = logits[lane & 15];
        float m = l;
#pragma unroll
        for (int o = 8; o; o >>= 1) m = fmaxf(m, __shfl_xor_sync(0xffffffffu, m, o));
        float e = __expf(l - m);
        float s = e;
#pragma unroll
        for (int o = 8; o; o >>= 1) s += __shfl_xor_sync(0xffffffffu, s, o);
        if (lane < 16) g_lr[b * Uq + lane] = e / s;
    }
}

// ---------------------------------------------------------------------------
// Kernel 2: fused state update.  BM=128 BN=128 BK=32, 3-stage cp.async.
// 8 warps as 2(m) x 4(n); warp tile 64x32 = 4x4 m16n8k8.
// A smem [m][36] (raw fp32 bits -> tf32 by HW truncation)
// B smem [k][136]
// sr folded into A fragments for the echo (k>=Dq) stages.
// ---------------------------------------------------------------------------
#define AS 36
#define BS 136
#define ST_STAGE_A (128 * AS)
#define ST_STAGE_B (32 * BS)

__global__ void __launch_bounds__(256, 1) state_kernel(
    const float* __restrict__ X, const float* __restrict__ state,
    const float* __restrict__ W, const float* __restrict__ Win,
    const float* __restrict__ bias, const float* __restrict__ sr,
    float* __restrict__ out_ns)
{
    extern __shared__ float smem[];
    float* sA = smem;                    // 3 * 128*36
    float* sB = smem + 3 * ST_STAGE_A;   // 3 * 32*136

    const int u  = blockIdx.z;
    const int n0 = blockIdx.x * 128;
    const float srv = sr[u];

    const int t      = threadIdx.x;
    const int wid    = t >> 5;
    const int lane   = t & 31;
    const int gid    = lane >> 2;
    const int tig    = lane & 3;
    const int m_warp = (wid >> 2) * 64;  // 0,64
    const int n_warp = (wid & 3) * 32;   // 0..96

    // loader mappings
    const int la_m = t >> 3;             // + i*32, i=0..3
    const int la_k = (t & 7) << 2;       // 0..28
    const int lb_k = t >> 5;             // + i*8
    const int lb_n = (t & 31) << 2;      // 0..124

    float acc[4][4][4] = {};

#define ST_LOAD(KT, SI)                                                          \
    do {                                                                         \
        float* As_ = sA + (SI) * ST_STAGE_A;                                     \
        float* Bs_ = sB + (SI) * ST_STAGE_B;                                     \
        if ((KT) < Dq) {                                                         \
            _Pragma("unroll")                                                    \
            for (int i_ = 0; i_ < 4; i_++) {                                     \
                int m_ = la_m + i_ * 32;                                         \
                cp16(As_ + m_ * AS + la_k,                                       \
                     X + ((size_t)m_ * Uq + u) * Dq + (KT) + la_k);              \
            }                                                                    \
            _Pragma("unroll")                                                    \
            for (int i_ = 0; i_ < 4; i_++) {                                     \
                int k_ = lb_k + i_ * 8;                                          \
                cp16(Bs_ + k_ * BS + lb_n,                                       \
                     Win + ((size_t)u * Dq + (KT) + k_) * Nq + n0 + lb_n);       \
            }                                                                    \
        } else {                                                                 \
            _Pragma("unroll")                                                    \
            for (int i_ = 0; i_ < 4; i_++) {                                     \
                int m_ = la_m + i_ * 32;                                         \
                cp16(As_ + m_ * AS + la_k,                                       \
                     state + ((size_t)m_ * Uq + u) * Nq + (KT) - Dq + la_k);     \
            }                                                                    \
            _Pragma("unroll")                                                    \
            for (int i_ = 0; i_ < 4; i_++) {                                     \
                int k_ = lb_k + i_ * 8;                                          \
                cp16(Bs_ + k_ * BS + lb_n,                                       \
                     W + ((size_t)u * Nq + (KT) - Dq + k_) * Nq + n0 + lb_n);    \
            }                                                                    \
        }                                                                        \
    } while (0)

    ST_LOAD(0, 0);  CP_COMMIT();
    ST_LOAD(32, 1); CP_COMMIT();

    const int ITERS = (Dq + Nq) / 32;   // 40
    for (int i = 0; i < ITERS; i++) {
        CP_WAIT1();
        __syncthreads();
        const int pf = i + 2;
        if (pf < ITERS) ST_LOAD(pf * 32, pf % 3);
        CP_COMMIT();

        const int si = i % 3;
        const float* As_ = sA + si * ST_STAGE_A;
        const float* Bs_ = sB + si * ST_STAGE_B;
        const bool echo = (i * 32) >= Dq;

#pragma unroll
        for (int ks = 0; ks < 4; ks++) {
            const int kb = ks * 8;
            float a[4][4], b[4][2];
#pragma unroll
            for (int mt = 0; mt < 4; mt++) {
                const int m = m_warp + mt * 16 + gid;
                a[mt][0] = As_[(m) * AS + kb + tig];
                a[mt][1] = As_[(m + 8) * AS + kb + tig];
                a[mt][2] = As_[(m) * AS + kb + tig + 4];
                a[mt][3] = As_[(m + 8) * AS + kb + tig + 4];
            }
            if (echo) {
#pragma unroll
                for (int mt = 0; mt < 4; mt++)
#pragma unroll
                    for (int r = 0; r < 4; r++) a[mt][r] *= srv;
            }
#pragma unroll
            for (int nt = 0; nt < 4; nt++) {
                const int n = n_warp + nt * 8 + gid;
                b[nt][0] = Bs_[(kb + tig) * BS + n];
                b[nt][1] = Bs_[(kb + tig + 4) * BS + n];
            }
#pragma unroll
            for (int mt = 0; mt < 4; mt++)
#pragma unroll
                for (int nt = 0; nt < 4; nt++)
                    mma_tf32(acc[mt][nt], a[mt], b[nt]);
        }
    }

    // epilogue: bias, tanh, lr-gated update
#pragma unroll
    for (int mt = 0; mt < 4; mt++) {
#pragma unroll
        for (int half = 0; half < 2; half++) {
            const int bb = m_warp + mt * 16 + gid + half * 8;
            const float lr  = g_lr[bb * Uq + u];
            const float oml = 1.f - lr;
            const float* srow = state  + ((size_t)bb * Uq + u) * Nq;
            float*       orow = out_ns + ((size_t)bb * Uq + u) * Nq;
#pragma unroll
            for (int nt = 0; nt < 4; nt++) {
                const int n = n0 + n_warp + nt * 8 + tig * 2;
#pragma unroll
                for (int j = 0; j < 2; j++) {
                    const float v = acc[mt][nt][half * 2 + j] + bias[u * Nq + n + j];
                    orow[n + j] = oml * srow[n + j] + lr * fast_tanh(v);
                }
            }
        }
    }
}

// ---------------------------------------------------------------------------
// Kernel 3: output = new_state @ Wout[u].  BM=64 BN=64 BK=32, 3 stages,
// 128 threads = 4 warps 2x2, warp tile 32x32.
// ---------------------------------------------------------------------------
#define OAS 36
#define OBS 72
#define O_STAGE_A (64 * OAS)
#define O_STAGE_B (32 * OBS)

__global__ void __launch_bounds__(128, 1) out_kernel(
    const float* __restrict__ ns, const float* __restrict__ Wout,
    float* __restrict__ out2)
{
    extern __shared__ float smem[];
    float* sA = smem;
    float* sB = smem + 3 * O_STAGE_A;

    const int u  = blockIdx.z;
    const int o0 = blockIdx.x * 64;
    const int b0 = blockIdx.y * 64;

    const int t      = threadIdx.x;
    const int wid    = t >> 5;
    const int lane   = t & 31;
    const int gid    = lane >> 2;
    const int tig    = lane & 3;
    const int m_warp = (wid >> 1) * 32;
    const int n_warp = (wid & 1) * 32;

    const int la_m = t >> 3;          // + i*16
    const int la_k = (t & 7) << 2;
    const int lb_k = t >> 4;          // + i*8
    const int lb_n = (t & 15) << 2;

    float acc[2][4][4] = {};

#define O_LOAD(KT, SI)                                                       \
    do {                                                                     \
        float* As_ = sA + (SI) * O_STAGE_A;                                  \
        float* Bs_ = sB + (SI) * O_STAGE_B;                                  \
        _Pragma("unroll")                                                    \
        for (int i_ = 0; i_ < 4; i_++) {                                     \
            int m_ = la_m + i_ * 16;                                         \
            cp16(As_ + m_ * OAS + la_k,                                      \
                 ns + ((size_t)(b0 + m_) * Uq + u) * Nq + (KT) + la_k);      \
        }                                                                    \
        _Pragma("unroll")                                                    \
        for (int i_ = 0; i_ < 4; i_++) {                                     \
            int k_ = lb_k + i_ * 8;                                          \
            cp16(Bs_ + k_ * OBS + lb_n,                                      \
                 Wout + ((size_t)u * Nq + (KT) + k_) * Oq + o0 + lb_n);      \
        }                                                                    \
    } while (0)

    O_LOAD(0, 0);  CP_COMMIT();
    O_LOAD(32, 1); CP_COMMIT();

    const int ITERS = Nq / 32;   // 32
    for (int i = 0; i < ITERS; i++) {
        CP_WAIT1();
        __syncthreads();
        const int pf = i + 2;
        if (pf < ITERS) O_LOAD(pf * 32, pf % 3);
        CP_COMMIT();

        const int si = i % 3;
        const float* As_ = sA + si * O_STAGE_A;
        const float* Bs_ = sB + si * O_STAGE_B;

#pragma unroll
        for (int ks = 0; ks < 4; ks++) {
            const int kb = ks * 8;
            float a[2][4], b[4][2];
#pragma unroll
            for (int mt = 0; mt < 2; mt++) {
                const int m = m_warp + mt * 16 + gid;
                a[mt][0] = As_[(m) * OAS + kb + tig];
                a[mt][1] = As_[(m + 8) * OAS + kb + tig];
                a[mt][2] = As_[(m) * OAS + kb + tig + 4];
                a[mt][3] = As_[(m + 8) * OAS + kb + tig + 4];
            }
#pragma unroll
            for (int nt = 0; nt < 4; nt++) {
                const int n = n_warp + nt * 8 + gid;
                b[nt][0] = Bs_[(kb + tig) * OBS + n];
                b[nt][1] = Bs_[(kb + tig + 4) * OBS + n];
            }
#pragma unroll
            for (int mt = 0; mt < 2; mt++)
#pragma unroll
                for (int nt = 0; nt < 4; nt++)
                    mma_tf32(acc[mt][nt], a[mt], b[nt]);
        }
    }

#pragma unroll
    for (int mt = 0; mt < 2; mt++) {
#pragma unroll
        for (int half = 0; half < 2; half++) {
            const int bb = b0 + m_warp + mt * 16 + gid + half * 8;
            float* orow = out2 + ((size_t)bb * Uq + u) * Oq;
#pragma unroll
            for (int nt = 0; nt < 4; nt++) {
                const int n = o0 + n_warp + nt * 8 + tig * 2;
                orow[n + 0] = acc[mt][nt][half * 2 + 0];
                orow[n + 1] = acc[mt][nt][half * 2 + 1];
            }
        }
    }
}

// ---------------------------------------------------------------------------
extern "C" void kernel_launch(void* const* d_in, const int* in_sizes, int n_in,
                              void* d_out, int out_size) {
    const float* X     = (const float*)d_in[0];
    const float* state = (const float*)d_in[1];
    const float* W     = (const float*)d_in[2];
    const float* Win   = (const float*)d_in[3];
    const float* bias  = (const float*)d_in[4];
    const float* Wout  = (const float*)d_in[5];
    const float* sr    = (const float*)d_in[6];
    const float* alr   = (const float*)d_in[7];
    const float* temp  = (const float*)d_in[8];

    float* out_ns = (float*)d_out;                  // (B,U,N)
    float* out_o  = out_ns + (size_t)Bq * Uq * Nq;  // (B,U,O)

    const int st_smem = 3 * (ST_STAGE_A + ST_STAGE_B) * (int)sizeof(float); // 107520
    const int o_smem  = 3 * (O_STAGE_A + O_STAGE_B) * (int)sizeof(float);   //  55296
    // Idempotent, called every time (no static guards per harness rules).
    cudaFuncSetAttribute(state_kernel, cudaFuncAttributeMaxDynamicSharedMemorySize, st_smem);
    cudaFuncSetAttribute(out_kernel,   cudaFuncAttributeMaxDynamicSharedMemorySize, o_smem);

    lr_kernel<<<Bq, dim3(32, Uq)>>>(X, alr, temp);
    state_kernel<<<dim3(Nq / 128, 1, Uq), 256, st_smem>>>(X, state, W, Win, bias, sr, out_ns);
    out_kernel<<<dim3(Oq / 64, Bq / 64, Uq), 128, o_smem>>>(out_ns, Wout, out_o);
}